// round 1
// baseline (speedup 1.0000x reference)
#include <cuda_runtime.h>

// SpatialTransformer: 3D trilinear warp with dense displacement field.
// vol: [B=2, X=160, Y=192, Z=160, 1] f32
// trf: [B=2, X=160, Y=192, Z=160, 3] f32  (displacement, 'ij' indexing)
// out: [B=2, X=160, Y=192, Z=160, 1] f32
//
// Semantics (match JAX reference exactly):
//   loc  = grid + trf, clipped to [0, dim-1]
//   i0   = floor(loc)            (already in range after clip)
//   i1   = min(i0 + 1, dim-1)
//   w_lo = float(i1) - loc       (d1 in reference)
//   w_hi = 1 - w_lo              (d0 in reference)
//   out  = sum over 8 corners of prod(weights) * vol[corner]

#define DX 160
#define DY 192
#define DZ 160
#define NB 2

__global__ __launch_bounds__(256)
void warp_kernel(const float* __restrict__ vol,
                 const float* __restrict__ trf,
                 float* __restrict__ out)
{
    // Each thread handles 4 consecutive z voxels -> float4 I/O.
    const int ZG = DZ / 4;                       // 40 groups along z
    const int ngroups = NB * DX * DY * ZG;       // 2,457,600
    int i = blockIdx.x * blockDim.x + threadIdx.x;
    if (i >= ngroups) return;

    int zg = i % ZG;
    int t  = i / ZG;
    int y  = t % DY;
    t     /= DY;
    int x  = t % DX;
    int b  = t / DX;

    // trf for 4 voxels = 12 contiguous floats = 3 float4 (16B aligned: 48B * i)
    const float4* trf4 = reinterpret_cast<const float4*>(trf);
    float4 t0 = trf4[(size_t)i * 3 + 0];
    float4 t1 = trf4[(size_t)i * 3 + 1];
    float4 t2 = trf4[(size_t)i * 3 + 2];

    float tx[4] = {t0.x, t0.w, t1.z, t2.y};
    float ty[4] = {t0.y, t1.x, t1.w, t2.z};
    float tz[4] = {t0.z, t1.y, t2.x, t2.w};

    const float* __restrict__ v = vol + (size_t)b * (DX * DY * DZ);
    int zbase = zg * 4;

    float4 res;
    float* rp = reinterpret_cast<float*>(&res);

#pragma unroll
    for (int j = 0; j < 4; ++j) {
        // sample location, clipped to volume
        float lx = fminf(fmaxf((float)x + tx[j],          0.0f), (float)(DX - 1));
        float ly = fminf(fmaxf((float)y + ty[j],          0.0f), (float)(DY - 1));
        float lz = fminf(fmaxf((float)(zbase + j) + tz[j], 0.0f), (float)(DZ - 1));

        int ix0 = (int)floorf(lx);
        int iy0 = (int)floorf(ly);
        int iz0 = (int)floorf(lz);
        int ix1 = min(ix0 + 1, DX - 1);
        int iy1 = min(iy0 + 1, DY - 1);
        int iz1 = min(iz0 + 1, DZ - 1);

        // lower-corner weights (d1 in reference), upper = 1 - lower
        float wx1 = (float)ix1 - lx;
        float wy1 = (float)iy1 - ly;
        float wz1 = (float)iz1 - lz;
        float wx0 = 1.0f - wx1;
        float wy0 = 1.0f - wy1;
        float wz0 = 1.0f - wz1;

        const float* p00 = v + ((size_t)ix0 * DY + iy0) * DZ;
        const float* p01 = v + ((size_t)ix0 * DY + iy1) * DZ;
        const float* p10 = v + ((size_t)ix1 * DY + iy0) * DZ;
        const float* p11 = v + ((size_t)ix1 * DY + iy1) * DZ;

        float v000 = __ldg(p00 + iz0), v001 = __ldg(p00 + iz1);
        float v010 = __ldg(p01 + iz0), v011 = __ldg(p01 + iz1);
        float v100 = __ldg(p10 + iz0), v101 = __ldg(p10 + iz1);
        float v110 = __ldg(p11 + iz0), v111 = __ldg(p11 + iz1);

        // interpolate along z, then y, then x
        float c00 = v000 * wz1 + v001 * wz0;
        float c01 = v010 * wz1 + v011 * wz0;
        float c10 = v100 * wz1 + v101 * wz0;
        float c11 = v110 * wz1 + v111 * wz0;

        float c0 = c00 * wy1 + c01 * wy0;
        float c1 = c10 * wy1 + c11 * wy0;

        rp[j] = c0 * wx1 + c1 * wx0;
    }

    reinterpret_cast<float4*>(out)[i] = res;
}

extern "C" void kernel_launch(void* const* d_in, const int* in_sizes, int n_in,
                              void* d_out, int out_size)
{
    const float* vol = (const float*)d_in[0];
    const float* trf = (const float*)d_in[1];
    float* out = (float*)d_out;

    const int ngroups = NB * DX * DY * (DZ / 4);   // 2,457,600
    const int threads = 256;
    const int blocks  = (ngroups + threads - 1) / threads;  // 9600
    warp_kernel<<<blocks, threads>>>(vol, trf, out);
}